// round 3
// baseline (speedup 1.0000x reference)
#include <cuda_runtime.h>

// ARModel: self-feeding AR(P), k=4 linearized expansion + f32x2 packing.
//
// pred_{t+m} = c^m . h_t + beta_m * bias,  h_t = 12-entry window (oldest first)
//   c^0 = a
//   c^{m+1}[0] = c^m[11]*a[0];  c^{m+1}[j] = c^m[11]*a[j] + c^m[j-1]
//   beta_0 = 1;  beta_{m+1} = beta_m + c^m[11]
// Each phase emits k=4 predictions from one window -> 4 independent 12-FMA
// chains; dependent-op reissue gap = 4 instr >= FFMA2 latency.
//
// Thread handles two adjacent nodes packed in f32x2 lanes; all global traffic
// is 8-byte and warp-coalesced. Stores use one per-round base pointer with
// compile-time offsets (no per-phase pointer arithmetic).

constexpr int Bd = 64;
constexpr int Td = 288;
constexpr int Nd = 1024;
constexpr int Pd = 12;
constexpr int K  = 4;              // steps per phase
static_assert(Td % Pd == 0 && Pd % K == 0, "unroll structure");

typedef unsigned long long u64;

__device__ __forceinline__ u64 pack2(float lo, float hi) {
    u64 r; asm("mov.b64 %0, {%1, %2};" : "=l"(r) : "f"(lo), "f"(hi)); return r;
}
__device__ __forceinline__ u64 fma2(u64 a, u64 b, u64 c) {
    u64 d; asm("fma.rn.f32x2 %0, %1, %2, %3;" : "=l"(d) : "l"(a), "l"(b), "l"(c)); return d;
}
__device__ __forceinline__ u64 mul2(u64 a, u64 b) {
    u64 d; asm("mul.rn.f32x2 %0, %1, %2;" : "=l"(d) : "l"(a), "l"(b)); return d;
}

__global__ void __launch_bounds__(32)
ar_model_k4_kernel(const float* __restrict__ x,
                   const float* __restrict__ ar,
                   const float* __restrict__ bias,
                   float* __restrict__ out)
{
    const int tid = blockIdx.x * 32 + threadIdx.x;   // 0 .. 32767
    const int b   = tid >> 9;                        // batch
    const int pr  = tid & 511;                       // node pair
    const int n0  = pr * 2;

    // ---- pack per-node AR coefficients ----
    float alo[Pd], ahi[Pd];
#pragma unroll
    for (int j = 0; j < Pd; ++j) {
        alo[j] = ar[n0 * Pd + j];
        ahi[j] = ar[(n0 + 1) * Pd + j];
    }
    u64 a[Pd];
#pragma unroll
    for (int j = 0; j < Pd; ++j) a[j] = pack2(alo[j], ahi[j]);

    // ---- expanded coefficient rows c1 = aM, c2 = aM^2, c3 = aM^3 ----
    u64 c1[Pd], c2[Pd], c3[Pd];
    c1[0] = mul2(a[Pd - 1], a[0]);
#pragma unroll
    for (int j = 1; j < Pd; ++j) c1[j] = fma2(a[Pd - 1], a[j], a[j - 1]);
    c2[0] = mul2(c1[Pd - 1], a[0]);
#pragma unroll
    for (int j = 1; j < Pd; ++j) c2[j] = fma2(c1[Pd - 1], a[j], c1[j - 1]);
    c3[0] = mul2(c2[Pd - 1], a[0]);
#pragma unroll
    for (int j = 1; j < Pd; ++j) c3[j] = fma2(c2[Pd - 1], a[j], c2[j - 1]);

    // ---- bias premultipliers: bb_m = beta_m * bias ----
    //   beta_0 = 1; beta_{m+1} = beta_m + c^m[11]
    const float blo = bias[n0], bhi = bias[n0 + 1];
    const float b1lo = 1.0f + alo[11],  b1hi = 1.0f + ahi[11];
    float c1_11_lo, c1_11_hi, c2_11_lo, c2_11_hi;
    asm("mov.b64 {%0, %1}, %2;" : "=f"(c1_11_lo), "=f"(c1_11_hi) : "l"(c1[11]));
    asm("mov.b64 {%0, %1}, %2;" : "=f"(c2_11_lo), "=f"(c2_11_hi) : "l"(c2[11]));
    const float b2lo = b1lo + c1_11_lo, b2hi = b1hi + c1_11_hi;
    const float b3lo = b2lo + c2_11_lo, b3hi = b2hi + c2_11_hi;
    const u64 bb0 = pack2(blo, bhi);
    const u64 bb1 = pack2(b1lo * blo, b1hi * bhi);
    const u64 bb2 = pack2(b2lo * blo, b2hi * bhi);
    const u64 bb3 = pack2(b3lo * blo, b3hi * bhi);

    // ---- initial history window (oldest first) ----
    u64 buf[Pd];
    const u64* xr = reinterpret_cast<const u64*>(
        x + ((size_t)b * Td + (Td - Pd)) * Nd + n0);
#pragma unroll
    for (int j = 0; j < Pd; ++j) buf[j] = xr[(size_t)j * (Nd / 2)];

    u64* o = reinterpret_cast<u64*>(out + (size_t)b * Td * Nd + n0);
    constexpr int ST = Nd / 2;                       // timestep stride in u64

#pragma unroll 2
    for (int r = 0; r < Td / Pd; ++r) {              // 24 rounds x 12 steps
#pragma unroll
        for (int ph = 0; ph < Pd / K; ++ph) {        // 3 phases, off = 0,4,8
            const int off = ph * K;
            u64 p0 = bb0, p1 = bb1, p2 = bb2, p3 = bb3;
#pragma unroll
            for (int j = 0; j < Pd; ++j) {
                const u64 h = buf[(off + j) % Pd];   // constant index post-unroll
                p0 = fma2(a[j],  h, p0);
                p1 = fma2(c1[j], h, p1);
                p2 = fma2(c2[j], h, p2);
                p3 = fma2(c3[j], h, p3);
            }
            buf[off]     = p0;                       // replace 4 oldest slots
            buf[off + 1] = p1;
            buf[off + 2] = p2;
            buf[off + 3] = p3;
            o[(size_t)(off + 0) * ST] = p0;          // compile-time offsets
            o[(size_t)(off + 1) * ST] = p1;
            o[(size_t)(off + 2) * ST] = p2;
            o[(size_t)(off + 3) * ST] = p3;
        }
        o += (size_t)Pd * ST;                        // one pointer bump / round
    }
}

extern "C" void kernel_launch(void* const* d_in, const int* in_sizes, int n_in,
                              void* d_out, int out_size)
{
    const float* x    = (const float*)d_in[0];  // (B, T, N, 1) fp32
    const float* ar   = (const float*)d_in[1];  // (N, P) fp32
    const float* bias = (const float*)d_in[2];  // (N,) fp32
    float* out = (float*)d_out;

    // 64 * 512 node-pairs = 32768 threads in 32-thread blocks -> 1024 blocks,
    // ~6.9 warps/SM with near-perfect wave balance.
    ar_model_k4_kernel<<<(Bd * (Nd / 2)) / 32, 32>>>(x, ar, bias, out);
}